// round 1
// baseline (speedup 1.0000x reference)
#include <cuda_runtime.h>

#define LENGTH   262144
#define NFFT     2048
#define HOP      512
#define BATCH    16
#define FRAMES   513        // (262144)/512 + 1 after reflect pad 1024/1024
#define KHALF    1025       // bins 0..1024 computed, rest mirrored
#define TILE_K   128        // k-bins per block
#define TILE_F   32         // frames per block
#define CHUNK    32         // n-samples per smem chunk

__global__ __launch_bounds__(256, 3) void dft_kernel(
    const float* __restrict__ x,
    const float* __restrict__ wsin,
    const float* __restrict__ wcos,
    float* __restrict__ out)
{
    __shared__ __align__(16) float sc[CHUNK][TILE_K];     // wcos tile, transposed [n][k]
    __shared__ __align__(16) float ss[CHUNK][TILE_K];     // wsin tile, transposed [n][k]
    __shared__ __align__(16) float sx[TILE_F][CHUNK + 1]; // frame samples [f][n]

    const int k0  = blockIdx.x * TILE_K;
    const int f0  = blockIdx.y * TILE_F;
    const int b   = blockIdx.z;
    const int tid = threadIdx.x;
    const int fcol = tid & 15;   // -> frames fcol*2, fcol*2+1
    const int krow = tid >> 4;   // -> k local krow*8 .. krow*8+7

    const float* __restrict__ xb = x + (size_t)b * LENGTH;

    float accC[8][2];
    float accS[8][2];
    #pragma unroll
    for (int i = 0; i < 8; i++) {
        accC[i][0] = 0.f; accC[i][1] = 0.f;
        accS[i][0] = 0.f; accS[i][1] = 0.f;
    }

    for (int n0 = 0; n0 < NFFT; n0 += CHUNK) {
        // ---- load W tiles (transpose [k][n] -> [n][k]) ----
        // 128 rows x 32 cols = 1024 float4 per matrix; 256 threads x 4
        #pragma unroll
        for (int r = 0; r < 4; r++) {
            int idx  = tid + r * 256;   // [0, 1024)
            int row  = idx >> 3;        // k local 0..127
            int col4 = idx & 7;         // n-group 0..7
            size_t g = (size_t)(k0 + row) * NFFT + n0 + col4 * 4;
            float4 c4 = *(const float4*)(wcos + g);
            float4 s4 = *(const float4*)(wsin + g);
            sc[col4*4+0][row] = c4.x; sc[col4*4+1][row] = c4.y;
            sc[col4*4+2][row] = c4.z; sc[col4*4+3][row] = c4.w;
            ss[col4*4+0][row] = s4.x; ss[col4*4+1][row] = s4.y;
            ss[col4*4+2][row] = s4.z; ss[col4*4+3][row] = s4.w;
        }
        // ---- load x tile with fused reflect padding ----
        // 32 frames x 32 samples = 1024 floats; 256 threads x 4
        #pragma unroll
        for (int r = 0; r < 4; r++) {
            int idx = tid + r * 256;    // [0, 1024)
            int f   = idx >> 5;         // 0..31
            int j   = idx & 31;         // 0..31
            long gi = (long)(f0 + f) * HOP + n0 + j - (NFFT / 2);
            if (gi < 0)        gi = -gi;
            if (gi >= LENGTH)  gi = 2L * LENGTH - 2 - gi;
            sx[f][j] = xb[gi];
        }
        __syncthreads();

        // ---- 32-step inner product ----
        #pragma unroll
        for (int j = 0; j < CHUNK; j++) {
            float x0 = sx[fcol*2 + 0][j];
            float x1 = sx[fcol*2 + 1][j];
            float4 c0 = *(const float4*)&sc[j][krow*8];
            float4 c1 = *(const float4*)&sc[j][krow*8 + 4];
            float4 s0 = *(const float4*)&ss[j][krow*8];
            float4 s1 = *(const float4*)&ss[j][krow*8 + 4];
            float cv[8] = {c0.x, c0.y, c0.z, c0.w, c1.x, c1.y, c1.z, c1.w};
            float sv[8] = {s0.x, s0.y, s0.z, s0.w, s1.x, s1.y, s1.z, s1.w};
            #pragma unroll
            for (int i = 0; i < 8; i++) {
                accC[i][0] = fmaf(cv[i], x0, accC[i][0]);
                accC[i][1] = fmaf(cv[i], x1, accC[i][1]);
                accS[i][0] = fmaf(sv[i], x0, accS[i][0]);
                accS[i][1] = fmaf(sv[i], x1, accS[i][1]);
            }
        }
        __syncthreads();
    }

    // ---- epilogue: write k and its mirror (2048-k) ----
    const size_t TOT = (size_t)BATCH * NFFT * FRAMES;
    #pragma unroll
    for (int i = 0; i < 8; i++) {
        int k = k0 + krow * 8 + i;
        if (k >= KHALF) continue;
        #pragma unroll
        for (int j = 0; j < 2; j++) {
            int t = f0 + fcol * 2 + j;
            if (t >= FRAMES) continue;
            size_t o = ((size_t)b * NFFT + k) * FRAMES + t;
            out[o]       = accC[i][j];   // real
            out[TOT + o] = -accS[i][j];  // -imag
            if (k >= 1 && k <= NFFT/2 - 1) {
                size_t om = ((size_t)b * NFFT + (NFFT - k)) * FRAMES + t;
                out[om]       = accC[i][j];  // real mirrored (cos symmetric)
                out[TOT + om] = accS[i][j];  // -imag mirrored (sin antisymmetric)
            }
        }
    }
}

extern "C" void kernel_launch(void* const* d_in, const int* in_sizes, int n_in,
                              void* d_out, int out_size) {
    const float* x    = (const float*)d_in[0];
    const float* wsin = (const float*)d_in[1];
    const float* wcos = (const float*)d_in[2];
    float* out = (float*)d_out;

    dim3 grid((KHALF + TILE_K - 1) / TILE_K,   // 9
              (FRAMES + TILE_F - 1) / TILE_F,  // 17
              BATCH);                          // 16
    dft_kernel<<<grid, 256>>>(x, wsin, wcos, out);
}